// round 3
// baseline (speedup 1.0000x reference)
#include <cuda_runtime.h>
#include <cuda_bf16.h>
#include <math.h>

// Problem constants (fixed by the dataset)
#define BATCH 2
#define LSEQ  2048
#define EMB   1024
#define NLM   64           // num landmarks M
#define ROWS  (BATCH*LSEQ) // 4096

// ---------------- scratch (device globals; no allocation allowed) ----------
__device__ float g_vproj[ROWS * EMB];          // 16 MB
__device__ float g_ql[ROWS * NLM];             // 1 MB
__device__ float g_kl[ROWS * NLM];             // 1 MB
__device__ float g_attn[BATCH * LSEQ * LSEQ];  // 32 MB
__device__ float g_out2[ROWS * EMB];           // 16 MB

// ---------------- packed f32x2 helpers (Blackwell FFMA2) --------------------
__device__ __forceinline__ unsigned long long pack2(float x) {
    unsigned long long r;
    asm("mov.b64 %0, {%1, %1};" : "=l"(r) : "f"(x));
    return r;
}
__device__ __forceinline__ unsigned long long ffma2(
    unsigned long long a, unsigned long long b, unsigned long long c) {
    unsigned long long d;
    asm("fma.rn.f32x2 %0, %1, %2, %3;" : "=l"(d) : "l"(a), "l"(b), "l"(c));
    return d;
}
__device__ __forceinline__ void unpack2(unsigned long long v, float& lo, float& hi) {
    asm("mov.b64 {%0, %1}, %2;" : "=f"(lo), "=f"(hi) : "l"(v));
}

// ---------------- generic tiled SGEMM (f32x2, double-buffered) --------------
// C[z] = alpha * A[z] * op(B[z]) (+ bias)
// A: [M,K] row-major. TRANS_B: B is [N,K] row-major (C=A*B^T); else B is [K,N].
// All of M,N divisible by 128; K divisible by 16.
#define BM 128
#define BN 128
#define BKK 16
#define TM 8
#define TN 8
#define PAD 4   // keeps 16B alignment of rows; store conflicts <= 2-way

template<bool TRANS_B, bool BIAS>
__global__ void __launch_bounds__(256, 2) sgemm_kernel(
    const float* __restrict__ A, const float* __restrict__ B,
    const float* __restrict__ bias, float* __restrict__ C,
    int M, int N, int K, float alpha,
    long sA, long sB, long sC)
{
    A += (long)blockIdx.z * sA;
    B += (long)blockIdx.z * sB;
    C += (long)blockIdx.z * sC;

    __shared__ float As[2][BKK][BM + PAD];
    __shared__ float Bs[2][BKK][BN + PAD];

    const int tid = threadIdx.x;
    const int tx = tid % 16;       // n direction
    const int ty = tid / 16;       // m direction
    const int m0 = blockIdx.y * BM;
    const int n0 = blockIdx.x * BN;

    // per-thread global-load coordinates (2048 floats per 128x16 tile)
    const int lin0 = tid * 4;
    const int lin1 = tid * 4 + 1024;
    const int arA0 = lin0 / BKK, acA0 = lin0 % BKK;
    const int arA1 = lin1 / BKK, acA1 = lin1 % BKK;
    // B non-trans coordinates
    const int brB0 = lin0 / BN, bcB0 = lin0 % BN;
    const int brB1 = lin1 / BN, bcB1 = lin1 % BN;

    unsigned long long acc2[TM][TN / 2];
    #pragma unroll
    for (int i = 0; i < TM; i++)
        #pragma unroll
        for (int j = 0; j < TN / 2; j++) acc2[i][j] = 0ull;

    float4 ra0, ra1, rb0, rb1;

    // ---- load tile 0 into registers ----
    {
        const int k0 = 0;
        ra0 = *(const float4*)(A + (long)(m0 + arA0) * K + k0 + acA0);
        ra1 = *(const float4*)(A + (long)(m0 + arA1) * K + k0 + acA1);
        if (TRANS_B) {
            rb0 = *(const float4*)(B + (long)(n0 + arA0) * K + k0 + acA0);
            rb1 = *(const float4*)(B + (long)(n0 + arA1) * K + k0 + acA1);
        } else {
            rb0 = *(const float4*)(B + (long)(k0 + brB0) * N + n0 + bcB0);
            rb1 = *(const float4*)(B + (long)(k0 + brB1) * N + n0 + bcB1);
        }
    }
    // ---- store tile 0 to smem buf 0 ----
    {
        As[0][acA0 + 0][arA0] = ra0.x; As[0][acA0 + 1][arA0] = ra0.y;
        As[0][acA0 + 2][arA0] = ra0.z; As[0][acA0 + 3][arA0] = ra0.w;
        As[0][acA1 + 0][arA1] = ra1.x; As[0][acA1 + 1][arA1] = ra1.y;
        As[0][acA1 + 2][arA1] = ra1.z; As[0][acA1 + 3][arA1] = ra1.w;
        if (TRANS_B) {
            Bs[0][acA0 + 0][arA0] = rb0.x; Bs[0][acA0 + 1][arA0] = rb0.y;
            Bs[0][acA0 + 2][arA0] = rb0.z; Bs[0][acA0 + 3][arA0] = rb0.w;
            Bs[0][acA1 + 0][arA1] = rb1.x; Bs[0][acA1 + 1][arA1] = rb1.y;
            Bs[0][acA1 + 2][arA1] = rb1.z; Bs[0][acA1 + 3][arA1] = rb1.w;
        } else {
            *(float4*)&Bs[0][brB0][bcB0] = rb0;
            *(float4*)&Bs[0][brB1][bcB1] = rb1;
        }
    }
    __syncthreads();

    const int ntiles = K / BKK;
    for (int t = 0; t < ntiles; t++) {
        const int cur = t & 1;
        const int nxt = cur ^ 1;

        // ---- prefetch tile t+1 into registers (overlapped with compute) ----
        if (t + 1 < ntiles) {
            const int k0 = (t + 1) * BKK;
            ra0 = *(const float4*)(A + (long)(m0 + arA0) * K + k0 + acA0);
            ra1 = *(const float4*)(A + (long)(m0 + arA1) * K + k0 + acA1);
            if (TRANS_B) {
                rb0 = *(const float4*)(B + (long)(n0 + arA0) * K + k0 + acA0);
                rb1 = *(const float4*)(B + (long)(n0 + arA1) * K + k0 + acA1);
            } else {
                rb0 = *(const float4*)(B + (long)(k0 + brB0) * N + n0 + bcB0);
                rb1 = *(const float4*)(B + (long)(k0 + brB1) * N + n0 + bcB1);
            }
        }

        // ---- compute on buffer cur ----
        #pragma unroll
        for (int k = 0; k < BKK; k++) {
            float rm[TM];
            #pragma unroll
            for (int i = 0; i < TM; i += 4)
                *(float4*)&rm[i] = *(const float4*)&As[cur][k][ty * TM + i];
            unsigned long long rn2[TN / 2];
            *(ulonglong2*)&rn2[0] = *(const ulonglong2*)&Bs[cur][k][tx * TN];
            *(ulonglong2*)&rn2[2] = *(const ulonglong2*)&Bs[cur][k][tx * TN + 4];
            #pragma unroll
            for (int i = 0; i < TM; i++) {
                unsigned long long a2 = pack2(rm[i]);
                #pragma unroll
                for (int j = 0; j < TN / 2; j++)
                    acc2[i][j] = ffma2(a2, rn2[j], acc2[i][j]);
            }
        }

        // ---- commit prefetched tile to the other buffer ----
        if (t + 1 < ntiles) {
            As[nxt][acA0 + 0][arA0] = ra0.x; As[nxt][acA0 + 1][arA0] = ra0.y;
            As[nxt][acA0 + 2][arA0] = ra0.z; As[nxt][acA0 + 3][arA0] = ra0.w;
            As[nxt][acA1 + 0][arA1] = ra1.x; As[nxt][acA1 + 1][arA1] = ra1.y;
            As[nxt][acA1 + 2][arA1] = ra1.z; As[nxt][acA1 + 3][arA1] = ra1.w;
            if (TRANS_B) {
                Bs[nxt][acA0 + 0][arA0] = rb0.x; Bs[nxt][acA0 + 1][arA0] = rb0.y;
                Bs[nxt][acA0 + 2][arA0] = rb0.z; Bs[nxt][acA0 + 3][arA0] = rb0.w;
                Bs[nxt][acA1 + 0][arA1] = rb1.x; Bs[nxt][acA1 + 1][arA1] = rb1.y;
                Bs[nxt][acA1 + 2][arA1] = rb1.z; Bs[nxt][acA1 + 3][arA1] = rb1.w;
            } else {
                *(float4*)&Bs[nxt][brB0][bcB0] = rb0;
                *(float4*)&Bs[nxt][brB1][bcB1] = rb1;
            }
            __syncthreads();
        }
    }

    // ---- epilogue ----
    #pragma unroll
    for (int i = 0; i < TM; i++) {
        int m = m0 + ty * TM + i;
        #pragma unroll
        for (int j = 0; j < TN; j += 4) {
            int n = n0 + tx * TN + j;
            float4 bv4 = make_float4(0.f, 0.f, 0.f, 0.f);
            if (BIAS) bv4 = *(const float4*)(bias + n);
            float a0, a1, a2v, a3;
            unpack2(acc2[i][j / 2 + 0], a0, a1);
            unpack2(acc2[i][j / 2 + 1], a2v, a3);
            float4 v;
            v.x = a0  * alpha + bv4.x;
            v.y = a1  * alpha + bv4.y;
            v.z = a2v * alpha + bv4.z;
            v.w = a3  * alpha + bv4.w;
            *(float4*)(C + (long)m * N + n) = v;
        }
    }
}

// ---------------- landmark projection + softmax ----------------------------
// out[r, l] = softmax_l( (X[r,:]·Wl[l,:] + bl[l]) / 8 )
// One block handles 64 rows x 64 landmarks (full landmark dim -> fused softmax).
__global__ void __launch_bounds__(256) landmark_kernel(
    const float* __restrict__ X,    // [ROWS, 1024]
    const float* __restrict__ Wl,   // [64, 1024]
    const float* __restrict__ bl,   // [64]
    float* __restrict__ out)        // [ROWS, 64]
{
    __shared__ float Xs[16][64];
    __shared__ float Ws[16][64];
    __shared__ float S[64][65];

    const int tid = threadIdx.x;
    const int tx = tid % 16;   // landmark dir (16*4 = 64)
    const int ty = tid / 16;   // row dir
    const int r0 = blockIdx.x * 64;

    float acc[4][4];
    #pragma unroll
    for (int i = 0; i < 4; i++)
        #pragma unroll
        for (int j = 0; j < 4; j++) acc[i][j] = 0.f;

    const int lin = tid * 4;              // 1024 floats per tile
    const int lr = lin / 16, lc = lin % 16;

    for (int k0 = 0; k0 < EMB; k0 += 16) {
        float4 a = *(const float4*)(X + (long)(r0 + lr) * EMB + k0 + lc);
        Xs[lc + 0][lr] = a.x; Xs[lc + 1][lr] = a.y;
        Xs[lc + 2][lr] = a.z; Xs[lc + 3][lr] = a.w;
        float4 w = *(const float4*)(Wl + (long)lr * EMB + k0 + lc);
        Ws[lc + 0][lr] = w.x; Ws[lc + 1][lr] = w.y;
        Ws[lc + 2][lr] = w.z; Ws[lc + 3][lr] = w.w;
        __syncthreads();
        #pragma unroll
        for (int k = 0; k < 16; k++) {
            float rm[4], rn[4];
            #pragma unroll
            for (int i = 0; i < 4; i++) rm[i] = Xs[k][ty * 4 + i];
            #pragma unroll
            for (int j = 0; j < 4; j++) rn[j] = Ws[k][tx * 4 + j];
            #pragma unroll
            for (int i = 0; i < 4; i++)
                #pragma unroll
                for (int j = 0; j < 4; j++)
                    acc[i][j] += rm[i] * rn[j];
        }
        __syncthreads();
    }

    const float sc = 0.125f;  // 1/sqrt(M=64)
    #pragma unroll
    for (int i = 0; i < 4; i++)
        #pragma unroll
        for (int j = 0; j < 4; j++)
            S[ty * 4 + i][tx * 4 + j] = (acc[i][j] + bl[tx * 4 + j]) * sc;
    __syncthreads();

    if (tid < 64) {
        float mx = -1e30f;
        #pragma unroll 8
        for (int l = 0; l < 64; l++) mx = fmaxf(mx, S[tid][l]);
        float sum = 0.f;
        #pragma unroll 8
        for (int l = 0; l < 64; l++) sum += __expf(S[tid][l] - mx);
        float inv = 1.f / sum;
        #pragma unroll 8
        for (int l = 0; l < 64; l++)
            out[(long)(r0 + tid) * NLM + l] = __expf(S[tid][l] - mx) * inv;
    }
}

// ---------------- row softmax over 2048 (in place) --------------------------
__global__ void __launch_bounds__(256) softmax_rows_kernel(float* __restrict__ S)
{
    float* row = S + (long)blockIdx.x * LSEQ;
    const int tid = threadIdx.x;
    __shared__ float red[256];

    float v[8];
    #pragma unroll
    for (int i = 0; i < 8; i++) v[i] = row[tid + i * 256];

    float mx = v[0];
    #pragma unroll
    for (int i = 1; i < 8; i++) mx = fmaxf(mx, v[i]);
    red[tid] = mx; __syncthreads();
    for (int s = 128; s > 0; s >>= 1) {
        if (tid < s) red[tid] = fmaxf(red[tid], red[tid + s]);
        __syncthreads();
    }
    mx = red[0]; __syncthreads();

    float sum = 0.f;
    #pragma unroll
    for (int i = 0; i < 8; i++) { v[i] = __expf(v[i] - mx); sum += v[i]; }
    red[tid] = sum; __syncthreads();
    for (int s = 128; s > 0; s >>= 1) {
        if (tid < s) red[tid] += red[tid + s];
        __syncthreads();
    }
    float inv = 1.f / red[0];
    #pragma unroll
    for (int i = 0; i < 8; i++) row[tid + i * 256] = v[i] * inv;
}

// ---------------- launcher ---------------------------------------------------
extern "C" void kernel_launch(void* const* d_in, const int* in_sizes, int n_in,
                              void* d_out, int out_size)
{
    const float* query = (const float*)d_in[0];  // [2,2048,1024]
    const float* key   = (const float*)d_in[1];  // [2,2048,1024]
    const float* value = (const float*)d_in[2];  // [2,2048,1024]
    const float* Wv    = (const float*)d_in[3];  // [1024,1024]
    const float* bv    = (const float*)d_in[4];  // [1024]
    const float* Wl    = (const float*)d_in[5];  // [64,1024]
    const float* bl    = (const float*)d_in[6];  // [64]
    const float* Wo    = (const float*)d_in[7];  // [1024,1024]
    const float* bo    = (const float*)d_in[8];  // [1024]
    float* out = (float*)d_out;                  // [2,2048,1024]

    float *vproj, *ql, *kl, *attn, *out2;
    cudaGetSymbolAddress((void**)&vproj, g_vproj);
    cudaGetSymbolAddress((void**)&ql,    g_ql);
    cudaGetSymbolAddress((void**)&kl,    g_kl);
    cudaGetSymbolAddress((void**)&attn,  g_attn);
    cudaGetSymbolAddress((void**)&out2,  g_out2);

    // 1) landmark projections + softmax: ql, kl   [4096, 64]
    landmark_kernel<<<ROWS / 64, 256>>>(query, Wl, bl, ql);
    landmark_kernel<<<ROWS / 64, 256>>>(key,   Wl, bl, kl);

    // 2) vproj = value @ Wv^T + bv   [4096, 1024]
    {
        dim3 grid(EMB / BN, ROWS / BM, 1);
        sgemm_kernel<true, true><<<grid, 256>>>(
            value, Wv, bv, vproj, ROWS, EMB, EMB, 1.0f, 0, 0, 0);
    }

    // 3) S = (ql @ kl^T) / sqrt(64)   per batch  [2048, 2048]
    {
        dim3 grid(LSEQ / BN, LSEQ / BM, BATCH);
        sgemm_kernel<true, false><<<grid, 256>>>(
            ql, kl, nullptr, attn, LSEQ, LSEQ, NLM, 0.125f,
            (long)LSEQ * NLM, (long)LSEQ * NLM, (long)LSEQ * LSEQ);
    }

    // 4) softmax over key dim, in place on attn
    softmax_rows_kernel<<<BATCH * LSEQ, 256>>>(attn);

    // 5) out2 = attn @ vproj  per batch  [2048, 1024]
    {
        dim3 grid(EMB / BN, LSEQ / BM, BATCH);
        sgemm_kernel<false, false><<<grid, 256>>>(
            attn, vproj, nullptr, out2, LSEQ, EMB, LSEQ, 1.0f,
            (long)LSEQ * LSEQ, (long)LSEQ * EMB, (long)LSEQ * EMB);
    }

    // 6) out = out2 @ Wo^T + bo   [4096, 1024]
    {
        dim3 grid(EMB / BN, ROWS / BM, 1);
        sgemm_kernel<true, true><<<grid, 256>>>(
            out2, Wo, bo, out, ROWS, EMB, EMB, 1.0f, 0, 0, 0);
    }
}

// round 7
// speedup vs baseline: 2.8431x; 2.8431x over previous
#include <cuda_runtime.h>
#include <cuda_bf16.h>
#include <cstdint>
#include <math.h>

#define BATCH 2
#define LSEQ  2048
#define EMB   1024
#define NLM   64
#define ROWS  (BATCH*LSEQ)   // 4096

// ------------------- scratch (device globals; no allocation) ---------------
__device__ float g_vproj[ROWS * EMB];
__device__ float g_S[BATCH * LSEQ * LSEQ];
__device__ float g_out2[ROWS * EMB];
__device__ __nv_bfloat16 g_valh[ROWS * EMB],  g_vall[ROWS * EMB];
__device__ __nv_bfloat16 g_Wvh[EMB * EMB],    g_Wvl[EMB * EMB];
__device__ __nv_bfloat16 g_Woh[EMB * EMB],    g_Wol[EMB * EMB];
__device__ __nv_bfloat16 g_vTh[BATCH * EMB * LSEQ], g_vTl[BATCH * EMB * LSEQ];
__device__ __nv_bfloat16 g_qlh[ROWS * NLM],   g_qll[ROWS * NLM];
__device__ __nv_bfloat16 g_klh[ROWS * NLM],   g_kll[ROWS * NLM];
__device__ __nv_bfloat16 g_ah[BATCH * LSEQ * LSEQ], g_al[BATCH * LSEQ * LSEQ];
__device__ __nv_bfloat16 g_o2h[ROWS * EMB],   g_o2l[ROWS * EMB];

// ------------------- portable PTX helpers (sm_80+; legal on sm_103) --------
__device__ __forceinline__ uint32_t smem_u32(const void* p) {
    uint32_t a;
    asm("{ .reg .u64 t; cvta.to.shared.u64 t, %1; cvt.u32.u64 %0, t; }"
        : "=r"(a) : "l"(p));
    return a;
}
#define CP_ASYNC16(dst, src) \
    asm volatile("cp.async.cg.shared.global [%0], [%1], 16;" :: "r"(dst), "l"(src))
#define CP_COMMIT() asm volatile("cp.async.commit_group;" ::: "memory")
#define CP_WAIT1()  asm volatile("cp.async.wait_group 1;" ::: "memory")

__device__ __forceinline__ void ldsm_x4(uint32_t addr, uint32_t* r) {
    asm volatile("ldmatrix.sync.aligned.m8n8.x4.shared.b16 {%0,%1,%2,%3}, [%4];"
                 : "=r"(r[0]), "=r"(r[1]), "=r"(r[2]), "=r"(r[3]) : "r"(addr));
}
__device__ __forceinline__ void mma16816(float* c, const uint32_t* a, uint32_t b0, uint32_t b1) {
    asm volatile(
        "mma.sync.aligned.m16n8k16.row.col.f32.bf16.bf16.f32 "
        "{%0,%1,%2,%3}, {%4,%5,%6,%7}, {%8,%9}, {%0,%1,%2,%3};"
        : "+f"(c[0]), "+f"(c[1]), "+f"(c[2]), "+f"(c[3])
        : "r"(a[0]), "r"(a[1]), "r"(a[2]), "r"(a[3]), "r"(b0), "r"(b1));
}

// ------------------- mma.sync split-bf16 GEMM -------------------------------
// C[z] = alpha * (Ah+Al)[M,K] @ (Bh+Bl)[N,K]^T (+ bias), fp32 out.
// Both operands K-contiguous row-major bf16. M,N % 128 == 0, K % 32 == 0.
// Block 128x128, 8 warps (2m x 4n), warp tile 64x32, BK=32, 3-stage cp.async.
#define ROWB   80                       // smem row stride bytes (40 bf16, pad 32->40)
#define TILE_B (128 * ROWB)             // 10240 B per tile
#define STAGE_B (4 * TILE_B)            // Ah, Al, Bh, Bl
#define NSTG   3
#define GEMM_SMEM (NSTG * STAGE_B)      // 122880 B

__device__ __forceinline__ void prefetch_stage(
    uint32_t sb, int stage,
    const __nv_bfloat16* __restrict__ Ah, const __nv_bfloat16* __restrict__ Al,
    const __nv_bfloat16* __restrict__ Bh, const __nv_bfloat16* __restrict__ Bl,
    int K, int kc, int tid)
{
    const uint32_t base = sb + stage * STAGE_B;
    #pragma unroll
    for (int i = 0; i < 2; i++) {
        const int row = (tid >> 2) + i * 64;
        const int u   = tid & 3;
        const uint32_t d = base + row * ROWB + u * 16;
        const long  goff = (long)row * K + kc + u * 8;
        CP_ASYNC16(d + 0 * TILE_B, Ah + goff);
        CP_ASYNC16(d + 1 * TILE_B, Al + goff);
        CP_ASYNC16(d + 2 * TILE_B, Bh + goff);
        CP_ASYNC16(d + 3 * TILE_B, Bl + goff);
    }
}

template<bool BIAS>
__global__ void __launch_bounds__(256) tc_gemm(
    const __nv_bfloat16* __restrict__ Ah, const __nv_bfloat16* __restrict__ Al,
    const __nv_bfloat16* __restrict__ Bh, const __nv_bfloat16* __restrict__ Bl,
    const float* __restrict__ bias, float* __restrict__ C,
    int K, int Ntot, float alpha, long sA, long sB, long sC)
{
    extern __shared__ char smem[];
    const int tid  = threadIdx.x;
    const int wid  = tid >> 5, lane = tid & 31;
    const int wm   = wid >> 2;          // 0..1  (64-row slab)
    const int wn   = wid & 3;           // 0..3  (32-col slab)
    const int m0   = blockIdx.y * 128, n0 = blockIdx.x * 128;

    Ah += (long)blockIdx.z * sA + (long)m0 * K;
    Al += (long)blockIdx.z * sA + (long)m0 * K;
    Bh += (long)blockIdx.z * sB + (long)n0 * K;
    Bl += (long)blockIdx.z * sB + (long)n0 * K;
    C  += (long)blockIdx.z * sC;

    const uint32_t sb = smem_u32(smem);

    // ldmatrix per-lane offsets (bytes within a tile)
    const uint32_t offA = (uint32_t)((lane & 15) * ROWB + (lane >> 4) * 16);
    const uint32_t offB = (uint32_t)((((lane >> 4) << 3) | (lane & 7)) * ROWB
                                     + ((lane >> 3) & 1) * 16);

    float acc[4][4][4];
    #pragma unroll
    for (int mi = 0; mi < 4; mi++)
        #pragma unroll
        for (int ni = 0; ni < 4; ni++)
            #pragma unroll
            for (int r = 0; r < 4; r++) acc[mi][ni][r] = 0.f;

    const int T = K >> 5;               // BK = 32
    prefetch_stage(sb, 0, Ah, Al, Bh, Bl, K, 0, tid);
    CP_COMMIT();
    if (T > 1) prefetch_stage(sb, 1, Ah, Al, Bh, Bl, K, 32, tid);
    CP_COMMIT();

    for (int t = 0; t < T; t++) {
        CP_WAIT1();
        __syncthreads();
        if (t + 2 < T)
            prefetch_stage(sb, (t + 2) % NSTG, Ah, Al, Bh, Bl, K, (t + 2) * 32, tid);
        CP_COMMIT();

        const uint32_t stg = sb + (t % NSTG) * STAGE_B;
        const uint32_t sAh = stg + 0 * TILE_B, sAl = stg + 1 * TILE_B;
        const uint32_t sBh = stg + 2 * TILE_B, sBl = stg + 3 * TILE_B;

        #pragma unroll
        for (int ka = 0; ka < 2; ka++) {
            const uint32_t kb = ka * 32;    // 16 bf16 = 32 bytes
            uint32_t fah[4][4], fal[4][4], fbh[2][4], fbl[2][4];
            #pragma unroll
            for (int mi = 0; mi < 4; mi++) {
                const uint32_t ro = (uint32_t)((wm * 64 + mi * 16) * ROWB) + kb + offA;
                ldsm_x4(sAh + ro, fah[mi]);
                ldsm_x4(sAl + ro, fal[mi]);
            }
            #pragma unroll
            for (int p = 0; p < 2; p++) {
                const uint32_t ro = (uint32_t)((wn * 32 + p * 16) * ROWB) + kb + offB;
                ldsm_x4(sBh + ro, fbh[p]);
                ldsm_x4(sBl + ro, fbl[p]);
            }
            #pragma unroll
            for (int mi = 0; mi < 4; mi++)
                #pragma unroll
                for (int ni = 0; ni < 4; ni++) {
                    const int p = ni >> 1, q = (ni & 1) * 2;
                    mma16816(acc[mi][ni], fah[mi], fbh[p][q], fbh[p][q + 1]);
                    mma16816(acc[mi][ni], fah[mi], fbl[p][q], fbl[p][q + 1]);
                    mma16816(acc[mi][ni], fal[mi], fbh[p][q], fbh[p][q + 1]);
                }
        }
        __syncthreads();
    }

    // ---- epilogue: write accumulators straight to C ----
    #pragma unroll
    for (int mi = 0; mi < 4; mi++) {
        const int r0 = m0 + wm * 64 + mi * 16 + (lane >> 2);
        #pragma unroll
        for (int ni = 0; ni < 4; ni++) {
            const int col = n0 + wn * 32 + ni * 8 + (lane & 3) * 2;
            float b0 = 0.f, b1 = 0.f;
            if (BIAS) { b0 = bias[col]; b1 = bias[col + 1]; }
            float2 v0, v1;
            v0.x = acc[mi][ni][0] * alpha + b0;
            v0.y = acc[mi][ni][1] * alpha + b1;
            v1.x = acc[mi][ni][2] * alpha + b0;
            v1.y = acc[mi][ni][3] * alpha + b1;
            *(float2*)(C + (long)r0 * Ntot + col)       = v0;
            *(float2*)(C + (long)(r0 + 8) * Ntot + col) = v1;
        }
    }
}

// ------------------- fp32 -> (hi, lo) bf16 split ----------------------------
__device__ __forceinline__ void split1(float x, __nv_bfloat16& h, __nv_bfloat16& l) {
    h = __float2bfloat16(x);
    l = __float2bfloat16(x - __bfloat162float(h));
}

__global__ void __launch_bounds__(256) split_kernel(
    const float4* __restrict__ src, ushort4* __restrict__ h, ushort4* __restrict__ l, int n4)
{
    int i = blockIdx.x * blockDim.x + threadIdx.x;
    if (i >= n4) return;
    float4 v = src[i];
    __nv_bfloat16 hh, ll;
    ushort4 ho, lo;
    split1(v.x, hh, ll); ho.x = __bfloat16_as_ushort(hh); lo.x = __bfloat16_as_ushort(ll);
    split1(v.y, hh, ll); ho.y = __bfloat16_as_ushort(hh); lo.y = __bfloat16_as_ushort(ll);
    split1(v.z, hh, ll); ho.z = __bfloat16_as_ushort(hh); lo.z = __bfloat16_as_ushort(ll);
    split1(v.w, hh, ll); ho.w = __bfloat16_as_ushort(hh); lo.w = __bfloat16_as_ushort(ll);
    h[i] = ho; l[i] = lo;
}

// vproj [b][LSEQ][EMB] fp32 -> vprojT hi/lo bf16 [b][EMB][LSEQ]
__global__ void __launch_bounds__(256) transpose_split_kernel(
    const float* __restrict__ src, __nv_bfloat16* __restrict__ th, __nv_bfloat16* __restrict__ tl)
{
    __shared__ float t[32][33];
    const long zs = (long)blockIdx.z * LSEQ * EMB;
    const long zd = (long)blockIdx.z * EMB * LSEQ;
    const int x0 = blockIdx.x * 32;   // EMB
    const int y0 = blockIdx.y * 32;   // LSEQ
    for (int r = threadIdx.y; r < 32; r += 8)
        t[r][threadIdx.x] = src[zs + (long)(y0 + r) * EMB + x0 + threadIdx.x];
    __syncthreads();
    for (int r = threadIdx.y; r < 32; r += 8) {
        float v = t[threadIdx.x][r];
        __nv_bfloat16 h, l;
        split1(v, h, l);
        long o = zd + (long)(x0 + r) * LSEQ + y0 + threadIdx.x;
        th[o] = h; tl[o] = l;
    }
}

// ------------------- landmark projection + softmax (split bf16 out) ---------
__global__ void __launch_bounds__(256) landmark_kernel(
    const float* __restrict__ X, const float* __restrict__ Wl, const float* __restrict__ bl,
    __nv_bfloat16* __restrict__ outh, __nv_bfloat16* __restrict__ outl)
{
    __shared__ float Xs[16][64];
    __shared__ float Ws[16][64];
    __shared__ float S[64][65];

    const int tid = threadIdx.x;
    const int tx = tid % 16, ty = tid / 16;
    const int r0 = blockIdx.x * 64;

    float acc[4][4];
    #pragma unroll
    for (int i = 0; i < 4; i++)
        #pragma unroll
        for (int j = 0; j < 4; j++) acc[i][j] = 0.f;

    const int lin = tid * 4;
    const int lr = lin / 16, lc = lin % 16;

    for (int k0 = 0; k0 < EMB; k0 += 16) {
        float4 a = *(const float4*)(X + (long)(r0 + lr) * EMB + k0 + lc);
        Xs[lc + 0][lr] = a.x; Xs[lc + 1][lr] = a.y; Xs[lc + 2][lr] = a.z; Xs[lc + 3][lr] = a.w;
        float4 w = *(const float4*)(Wl + (long)lr * EMB + k0 + lc);
        Ws[lc + 0][lr] = w.x; Ws[lc + 1][lr] = w.y; Ws[lc + 2][lr] = w.z; Ws[lc + 3][lr] = w.w;
        __syncthreads();
        #pragma unroll
        for (int k = 0; k < 16; k++) {
            float rm[4], rn[4];
            #pragma unroll
            for (int i = 0; i < 4; i++) rm[i] = Xs[k][ty * 4 + i];
            #pragma unroll
            for (int j = 0; j < 4; j++) rn[j] = Ws[k][tx * 4 + j];
            #pragma unroll
            for (int i = 0; i < 4; i++)
                #pragma unroll
                for (int j = 0; j < 4; j++) acc[i][j] += rm[i] * rn[j];
        }
        __syncthreads();
    }

    const float sc = 0.125f;
    #pragma unroll
    for (int i = 0; i < 4; i++)
        #pragma unroll
        for (int j = 0; j < 4; j++)
            S[ty * 4 + i][tx * 4 + j] = (acc[i][j] + bl[tx * 4 + j]) * sc;
    __syncthreads();

    if (tid < 64) {
        float mx = -1e30f;
        #pragma unroll 8
        for (int l = 0; l < 64; l++) mx = fmaxf(mx, S[tid][l]);
        float sum = 0.f;
        #pragma unroll 8
        for (int l = 0; l < 64; l++) sum += __expf(S[tid][l] - mx);
        float inv = 1.f / sum;
        #pragma unroll 8
        for (int l = 0; l < 64; l++) {
            float p = __expf(S[tid][l] - mx) * inv;
            __nv_bfloat16 h, lo;
            split1(p, h, lo);
            outh[(long)(r0 + tid) * NLM + l] = h;
            outl[(long)(r0 + tid) * NLM + l] = lo;
        }
    }
}

// ------------------- row softmax over 2048 -> split bf16 --------------------
__global__ void __launch_bounds__(256) softmax_split_kernel(
    const float* __restrict__ S, __nv_bfloat16* __restrict__ ah, __nv_bfloat16* __restrict__ al)
{
    const long base = (long)blockIdx.x * LSEQ;
    const int tid = threadIdx.x;
    __shared__ float red[256];

    float v[8];
    #pragma unroll
    for (int i = 0; i < 8; i++) v[i] = S[base + tid + i * 256];

    float mx = v[0];
    #pragma unroll
    for (int i = 1; i < 8; i++) mx = fmaxf(mx, v[i]);
    red[tid] = mx; __syncthreads();
    for (int s = 128; s > 0; s >>= 1) {
        if (tid < s) red[tid] = fmaxf(red[tid], red[tid + s]);
        __syncthreads();
    }
    mx = red[0]; __syncthreads();

    float sum = 0.f;
    #pragma unroll
    for (int i = 0; i < 8; i++) { v[i] = __expf(v[i] - mx); sum += v[i]; }
    red[tid] = sum; __syncthreads();
    for (int s = 128; s > 0; s >>= 1) {
        if (tid < s) red[tid] += red[tid + s];
        __syncthreads();
    }
    const float inv = 1.f / red[0];
    #pragma unroll
    for (int i = 0; i < 8; i++) {
        float p = v[i] * inv;
        __nv_bfloat16 h, l;
        split1(p, h, l);
        ah[base + tid + i * 256] = h;
        al[base + tid + i * 256] = l;
    }
}

// ------------------- launcher ------------------------------------------------
extern "C" void kernel_launch(void* const* d_in, const int* in_sizes, int n_in,
                              void* d_out, int out_size)
{
    const float* query = (const float*)d_in[0];
    const float* key   = (const float*)d_in[1];
    const float* value = (const float*)d_in[2];
    const float* bv    = (const float*)d_in[4];
    const float* Wl    = (const float*)d_in[5];
    const float* bl    = (const float*)d_in[6];
    const float* bo    = (const float*)d_in[8];
    float* out = (float*)d_out;

    float *vproj, *S, *out2;
    __nv_bfloat16 *valh, *vall, *Wvh, *Wvl, *Woh, *Wol, *vTh, *vTl;
    __nv_bfloat16 *qlh, *qll, *klh, *kll, *ah, *al, *o2h, *o2l;
    cudaGetSymbolAddress((void**)&vproj, g_vproj);
    cudaGetSymbolAddress((void**)&S,     g_S);
    cudaGetSymbolAddress((void**)&out2,  g_out2);
    cudaGetSymbolAddress((void**)&valh,  g_valh); cudaGetSymbolAddress((void**)&vall, g_vall);
    cudaGetSymbolAddress((void**)&Wvh,   g_Wvh);  cudaGetSymbolAddress((void**)&Wvl,  g_Wvl);
    cudaGetSymbolAddress((void**)&Woh,   g_Woh);  cudaGetSymbolAddress((void**)&Wol,  g_Wol);
    cudaGetSymbolAddress((void**)&vTh,   g_vTh);  cudaGetSymbolAddress((void**)&vTl,  g_vTl);
    cudaGetSymbolAddress((void**)&qlh,   g_qlh);  cudaGetSymbolAddress((void**)&qll,  g_qll);
    cudaGetSymbolAddress((void**)&klh,   g_klh);  cudaGetSymbolAddress((void**)&kll,  g_kll);
    cudaGetSymbolAddress((void**)&ah,    g_ah);   cudaGetSymbolAddress((void**)&al,   g_al);
    cudaGetSymbolAddress((void**)&o2h,   g_o2h);  cudaGetSymbolAddress((void**)&o2l,  g_o2l);

    cudaFuncSetAttribute(tc_gemm<true>,  cudaFuncAttributeMaxDynamicSharedMemorySize, GEMM_SMEM);
    cudaFuncSetAttribute(tc_gemm<false>, cudaFuncAttributeMaxDynamicSharedMemorySize, GEMM_SMEM);

    // 0) split inputs to (hi, lo) bf16
    split_kernel<<<(ROWS * EMB / 4 + 255) / 256, 256>>>(
        (const float4*)value, (ushort4*)valh, (ushort4*)vall, ROWS * EMB / 4);
    split_kernel<<<(EMB * EMB / 4 + 255) / 256, 256>>>(
        (const float4*)d_in[3], (ushort4*)Wvh, (ushort4*)Wvl, EMB * EMB / 4);
    split_kernel<<<(EMB * EMB / 4 + 255) / 256, 256>>>(
        (const float4*)d_in[7], (ushort4*)Woh, (ushort4*)Wol, EMB * EMB / 4);

    // 1) landmark projections + softmax -> ql, kl (hi/lo bf16)
    landmark_kernel<<<ROWS / 64, 256>>>(query, Wl, bl, qlh, qll);
    landmark_kernel<<<ROWS / 64, 256>>>(key,   Wl, bl, klh, kll);

    // 2) vproj = value @ Wv^T + bv   [4096, 1024] fp32
    tc_gemm<true><<<dim3(EMB / 128, ROWS / 128, 1), 256, GEMM_SMEM>>>(
        valh, vall, Wvh, Wvl, bv, vproj, EMB, EMB, 1.0f, 0, 0, 0);

    // 2b) transpose+split vproj -> vprojT hi/lo [b][1024][2048]
    transpose_split_kernel<<<dim3(EMB / 32, LSEQ / 32, BATCH), dim3(32, 8)>>>(vproj, vTh, vTl);

    // 3) S = (ql @ kl^T) / 8   per batch [2048, 2048] fp32
    tc_gemm<false><<<dim3(LSEQ / 128, LSEQ / 128, BATCH), 256, GEMM_SMEM>>>(
        qlh, qll, klh, kll, nullptr, S, NLM, LSEQ, 0.125f,
        (long)LSEQ * NLM, (long)LSEQ * NLM, (long)LSEQ * LSEQ);

    // 4) softmax rows -> attn hi/lo bf16
    softmax_split_kernel<<<BATCH * LSEQ, 256>>>(S, ah, al);

    // 5) out2 = attn @ vproj   per batch [2048, 1024] fp32 (B = vprojT, K-major)
    tc_gemm<false><<<dim3(EMB / 128, LSEQ / 128, BATCH), 256, GEMM_SMEM>>>(
        ah, al, vTh, vTl, nullptr, out2, LSEQ, EMB, 1.0f,
        (long)LSEQ * LSEQ, (long)EMB * LSEQ, (long)LSEQ * EMB);

    // 5b) split out2
    split_kernel<<<(ROWS * EMB / 4 + 255) / 256, 256>>>(
        (const float4*)out2, (ushort4*)o2h, (ushort4*)o2l, ROWS * EMB / 4);

    // 6) out = out2 @ Wo^T + bo   [4096, 1024] fp32
    tc_gemm<true><<<dim3(EMB / 128, ROWS / 128, 1), 256, GEMM_SMEM>>>(
        o2h, o2l, Woh, Wol, bo, out, EMB, EMB, 1.0f, 0, 0, 0);
}